// round 3
// baseline (speedup 1.0000x reference)
#include <cuda_runtime.h>
#include <cstdint>
#include <math.h>

// Problem constants (B=4, S=2048, D=1024, H=4096, E=4, K=2)
#define EXPERTS 4
#define NTOK    8192
#define DIM     1024
#define HID     4096
#define MAXROWS (2*NTOK)   // each token appears in exactly K=2 expert buckets

// ---------------- device scratch (static: no runtime allocation) ----------------
__device__ int      d_cnt[EXPERTS];
__device__ int      d_off[EXPERTS];
__device__ float    d_tbuf[EXPERTS*DIM];     // t_e[d] = sum_h gelu(b1)[h] * w2[e,h,d]
__device__ float    d_g1[EXPERTS*HID];       // gelu(b1)
__device__ float    d_mconst[EXPERTS*DIM];   // -t_e[d]
__device__ float    d_csum[DIM];             // sum_e (t_e + b2_e)
__device__ int      d_btok[EXPERTS*NTOK];
__device__ float    d_bgate[EXPERTS*NTOK];
__device__ uint32_t d_hact[(size_t)MAXROWS*(size_t)HID]; // tf32 bit patterns, 268 MB

__device__ __forceinline__ float gelu_exact(float v) {
    return 0.5f * v * (1.f + erff(v * 0.70710678118654752f));
}

// ---------------- setup: zero counters/t-buffer, gelu(b1) ----------------
__global__ void setup_kernel(const float* __restrict__ b1) {
    int i = blockIdx.x * blockDim.x + threadIdx.x;
    if (i < EXPERTS) d_cnt[i] = 0;
    if (i < EXPERTS*DIM) d_tbuf[i] = 0.f;
    if (i < EXPERTS*HID) d_g1[i] = gelu_exact(b1[i]);
}

// t_e[d] partial sums: grid (DIM/256, HID/256, EXPERTS)
__global__ void c_partial_kernel(const float* __restrict__ w2) {
    int e  = blockIdx.z;
    int d  = blockIdx.x * 256 + threadIdx.x;
    int h0 = blockIdx.y * 256;
    const float* W = w2 + ((size_t)e*HID + h0) * DIM + d;
    const float* G = d_g1 + e*HID + h0;
    float acc = 0.f;
    #pragma unroll 4
    for (int h = 0; h < 256; h++) acc += G[h] * W[(size_t)h * DIM];
    atomicAdd(&d_tbuf[e*DIM + d], acc);
}

__global__ void csum_kernel(const float* __restrict__ b2) {
    int d = blockIdx.x * 256 + threadIdx.x;  // DIM threads
    float s = 0.f;
    #pragma unroll
    for (int e = 0; e < EXPERTS; e++) {
        float t = d_tbuf[e*DIM + d];
        d_mconst[e*DIM + d] = -t;
        s += t + b2[e*DIM + d];
    }
    d_csum[d] = s;
}

__global__ void out_init_kernel(float* __restrict__ out) {
    int i = blockIdx.x * 256 + threadIdx.x;   // NTOK*DIM threads
    out[i] = d_csum[i & (DIM - 1)];
}

// ---------------- routing: 1 warp per token ----------------
__global__ void routing_kernel(const float* __restrict__ x,
                               const float* __restrict__ wr,
                               const float* __restrict__ br) {
    int warp = (blockIdx.x * blockDim.x + threadIdx.x) >> 5;
    int lane = threadIdx.x & 31;
    if (warp >= NTOK) return;
    const float* xr = x + (size_t)warp * DIM;
    float a0 = 0.f, a1 = 0.f, a2 = 0.f, a3 = 0.f;
    for (int d = lane; d < DIM; d += 32) {
        float xv = xr[d];
        float4 w = *reinterpret_cast<const float4*>(wr + d*4);
        a0 += xv * w.x; a1 += xv * w.y; a2 += xv * w.z; a3 += xv * w.w;
    }
    #pragma unroll
    for (int o = 16; o > 0; o >>= 1) {
        a0 += __shfl_xor_sync(0xFFFFFFFFu, a0, o);
        a1 += __shfl_xor_sync(0xFFFFFFFFu, a1, o);
        a2 += __shfl_xor_sync(0xFFFFFFFFu, a2, o);
        a3 += __shfl_xor_sync(0xFFFFFFFFu, a3, o);
    }
    if (lane == 0) {
        float l[4] = { a0 + br[0], a1 + br[1], a2 + br[2], a3 + br[3] };
        int b0 = 0;
        #pragma unroll
        for (int j = 1; j < 4; j++) if (l[j] > l[b0]) b0 = j;
        int b1i = (b0 == 0) ? 1 : 0;
        #pragma unroll
        for (int j = 0; j < 4; j++) if (j != b0 && l[j] > l[b1i]) b1i = j;
        float ex  = expf(l[b1i] - l[b0]);
        float inv = 1.f / (1.f + ex);
        float g0 = inv, g1 = ex * inv;
        int p0 = atomicAdd(&d_cnt[b0], 1);
        d_btok[b0*NTOK + p0] = warp;  d_bgate[b0*NTOK + p0] = g0;
        int p1 = atomicAdd(&d_cnt[b1i], 1);
        d_btok[b1i*NTOK + p1] = warp; d_bgate[b1i*NTOK + p1] = g1;
    }
}

__global__ void offsets_kernel() {
    int s = 0;
    for (int e = 0; e < EXPERTS; e++) { d_off[e] = s; s += d_cnt[e]; }
}

// ---------------- tf32 warp-MMA helpers ----------------
__device__ __forceinline__ uint32_t f2tf(float f) {
    uint32_t r; asm("cvt.rna.tf32.f32 %0, %1;" : "=r"(r) : "f"(f)); return r;
}
__device__ __forceinline__ void mma8(float* c, const uint32_t* a, const uint32_t* b) {
    asm volatile("mma.sync.aligned.m16n8k8.row.col.f32.tf32.tf32.f32 "
        "{%0,%1,%2,%3}, {%4,%5,%6,%7}, {%8,%9}, {%0,%1,%2,%3};"
        : "+f"(c[0]), "+f"(c[1]), "+f"(c[2]), "+f"(c[3])
        : "r"(a[0]), "r"(a[1]), "r"(a[2]), "r"(a[3]), "r"(b[0]), "r"(b[1]));
}

// ---------------- GEMM1: H_act = gelu(X[gather] @ W1_e + b1_e) ----------------
// grid (HID/128, NTOK/128, EXPERTS), 256 threads
__global__ void __launch_bounds__(256)
gemm1_kernel(const float* __restrict__ x,
             const float* __restrict__ w1,
             const float* __restrict__ b1) {
    const int e   = blockIdx.z;
    const int cnt = d_cnt[e];
    const int mt  = blockIdx.y;
    if (mt * 128 >= cnt) return;
    const int nt  = blockIdx.x;
    const int off = d_off[e];

    __shared__ uint32_t As[128][36];
    __shared__ uint32_t Bs[32][132];

    const int tid  = threadIdx.x;
    const int lane = tid & 31;
    const int wid  = tid >> 5;
    const int wm   = wid & 1;    // 0..1 (64 rows each)
    const int wn   = wid >> 1;   // 0..3 (32 cols each)

    const float* Bp = w1 + (size_t)e * DIM * HID + (size_t)nt * 128;

    int tok[4];
    #pragma unroll
    for (int i = 0; i < 4; i++) {
        int row  = (tid >> 3) + i * 32;
        int slot = mt * 128 + row;
        tok[i] = (slot < cnt) ? d_btok[e*NTOK + slot] : -1;
    }
    const int c4 = (tid & 7) * 4;

    float acc[4][4][4];
    #pragma unroll
    for (int i = 0; i < 4; i++)
        #pragma unroll
        for (int j = 0; j < 4; j++)
            #pragma unroll
            for (int q = 0; q < 4; q++) acc[i][j][q] = 0.f;

    for (int k0 = 0; k0 < DIM; k0 += 32) {
        #pragma unroll
        for (int i = 0; i < 4; i++) {
            int row = (tid >> 3) + i * 32;
            float4 v = make_float4(0.f, 0.f, 0.f, 0.f);
            if (tok[i] >= 0)
                v = *reinterpret_cast<const float4*>(x + (size_t)tok[i]*DIM + k0 + c4);
            As[row][c4+0] = f2tf(v.x); As[row][c4+1] = f2tf(v.y);
            As[row][c4+2] = f2tf(v.z); As[row][c4+3] = f2tf(v.w);
        }
        #pragma unroll
        for (int i = 0; i < 4; i++) {
            int idx = tid + i * 256;
            int kr  = idx >> 5;
            int cc  = (idx & 31) * 4;
            float4 v = *reinterpret_cast<const float4*>(Bp + (size_t)(k0+kr)*HID + cc);
            Bs[kr][cc+0] = f2tf(v.x); Bs[kr][cc+1] = f2tf(v.y);
            Bs[kr][cc+2] = f2tf(v.z); Bs[kr][cc+3] = f2tf(v.w);
        }
        __syncthreads();
        #pragma unroll
        for (int ks = 0; ks < 4; ks++) {
            const int kk = ks * 8;
            uint32_t a[4][4], b[4][2];
            #pragma unroll
            for (int mi = 0; mi < 4; mi++) {
                int r  = wm*64 + mi*16 + (lane >> 2);
                int cA = kk + (lane & 3);
                a[mi][0] = As[r][cA];   a[mi][1] = As[r+8][cA];
                a[mi][2] = As[r][cA+4]; a[mi][3] = As[r+8][cA+4];
            }
            #pragma unroll
            for (int ni = 0; ni < 4; ni++) {
                int col = wn*32 + ni*8 + (lane >> 2);
                b[ni][0] = Bs[kk + (lane & 3)][col];
                b[ni][1] = Bs[kk + 4 + (lane & 3)][col];
            }
            #pragma unroll
            for (int mi = 0; mi < 4; mi++)
                #pragma unroll
                for (int ni = 0; ni < 4; ni++)
                    mma8(acc[mi][ni], a[mi], b[ni]);
        }
        __syncthreads();
    }

    // epilogue: +b1, exact gelu, store as tf32 bit patterns (GEMM2 A-operand)
    #pragma unroll
    for (int mi = 0; mi < 4; mi++) {
        int r0 = wm*64 + mi*16 + (lane >> 2);
        #pragma unroll
        for (int half = 0; half < 2; half++) {
            int r = r0 + half*8;
            int slot = mt*128 + r;
            if (slot >= cnt) continue;
            uint32_t* hrow = d_hact + (size_t)(off + slot) * HID;
            #pragma unroll
            for (int ni = 0; ni < 4; ni++) {
                int col = nt*128 + wn*32 + ni*8 + (lane & 3)*2;
                float bb0 = __ldg(&b1[e*HID + col]);
                float bb1 = __ldg(&b1[e*HID + col + 1]);
                float v0 = acc[mi][ni][half*2+0] + bb0;
                float v1 = acc[mi][ni][half*2+1] + bb1;
                hrow[col]   = f2tf(gelu_exact(v0));
                hrow[col+1] = f2tf(gelu_exact(v1));
            }
        }
    }
}

// ---------------- GEMM2: out[tok] += g * (H_act @ W2_e - t_e) ----------------
// grid (DIM/128, NTOK/128, EXPERTS), 256 threads
__global__ void __launch_bounds__(256)
gemm2_kernel(const float* __restrict__ w2, float* __restrict__ out) {
    const int e   = blockIdx.z;
    const int cnt = d_cnt[e];
    const int mt  = blockIdx.y;
    if (mt * 128 >= cnt) return;
    const int nt  = blockIdx.x;
    const int off = d_off[e];

    __shared__ uint32_t As[128][36];
    __shared__ uint32_t Bs[32][132];

    const int tid  = threadIdx.x;
    const int lane = tid & 31;
    const int wid  = tid >> 5;
    const int wm   = wid & 1;
    const int wn   = wid >> 1;

    const float* Bp = w2 + (size_t)e * HID * DIM + (size_t)nt * 128;

    int rvalid[4]; size_t abase[4];
    #pragma unroll
    for (int i = 0; i < 4; i++) {
        int row  = (tid >> 3) + i * 32;
        int slot = mt * 128 + row;
        int v = (slot < cnt);
        rvalid[i] = v;
        abase[i]  = (size_t)(off + (v ? slot : 0)) * HID;
    }
    const int c4 = (tid & 7) * 4;

    float acc[4][4][4];
    #pragma unroll
    for (int i = 0; i < 4; i++)
        #pragma unroll
        for (int j = 0; j < 4; j++)
            #pragma unroll
            for (int q = 0; q < 4; q++) acc[i][j][q] = 0.f;

    for (int k0 = 0; k0 < HID; k0 += 32) {
        #pragma unroll
        for (int i = 0; i < 4; i++) {
            int row = (tid >> 3) + i * 32;
            uint4 v = make_uint4(0u, 0u, 0u, 0u);
            if (rvalid[i])
                v = *reinterpret_cast<const uint4*>(d_hact + abase[i] + k0 + c4);
            As[row][c4+0] = v.x; As[row][c4+1] = v.y;
            As[row][c4+2] = v.z; As[row][c4+3] = v.w;
        }
        #pragma unroll
        for (int i = 0; i < 4; i++) {
            int idx = tid + i * 256;
            int kr  = idx >> 5;
            int cc  = (idx & 31) * 4;
            float4 v = *reinterpret_cast<const float4*>(Bp + (size_t)(k0+kr)*DIM + cc);
            Bs[kr][cc+0] = f2tf(v.x); Bs[kr][cc+1] = f2tf(v.y);
            Bs[kr][cc+2] = f2tf(v.z); Bs[kr][cc+3] = f2tf(v.w);
        }
        __syncthreads();
        #pragma unroll
        for (int ks = 0; ks < 4; ks++) {
            const int kk = ks * 8;
            uint32_t a[4][4], b[4][2];
            #pragma unroll
            for (int mi = 0; mi < 4; mi++) {
                int r  = wm*64 + mi*16 + (lane >> 2);
                int cA = kk + (lane & 3);
                a[mi][0] = As[r][cA];   a[mi][1] = As[r+8][cA];
                a[mi][2] = As[r][cA+4]; a[mi][3] = As[r+8][cA+4];
            }
            #pragma unroll
            for (int ni = 0; ni < 4; ni++) {
                int col = wn*32 + ni*8 + (lane >> 2);
                b[ni][0] = Bs[kk + (lane & 3)][col];
                b[ni][1] = Bs[kk + 4 + (lane & 3)][col];
            }
            #pragma unroll
            for (int mi = 0; mi < 4; mi++)
                #pragma unroll
                for (int ni = 0; ni < 4; ni++)
                    mma8(acc[mi][ni], a[mi], b[ni]);
        }
        __syncthreads();
    }

    #pragma unroll
    for (int mi = 0; mi < 4; mi++) {
        int r0 = wm*64 + mi*16 + (lane >> 2);
        #pragma unroll
        for (int ni = 0; ni < 4; ni++) {
            int col = nt*128 + wn*32 + ni*8 + (lane & 3)*2;
            float m0 = d_mconst[e*DIM + col];
            float m1 = d_mconst[e*DIM + col + 1];
            #pragma unroll
            for (int half = 0; half < 2; half++) {
                int slot = mt*128 + r0 + half*8;
                if (slot >= cnt) continue;
                int   tk = d_btok[e*NTOK + slot];
                float g  = d_bgate[e*NTOK + slot];
                float* orow = out + (size_t)tk * DIM;
                atomicAdd(&orow[col],     (acc[mi][ni][half*2+0] + m0) * g);
                atomicAdd(&orow[col + 1], (acc[mi][ni][half*2+1] + m1) * g);
            }
        }
    }
}

// ---------------- launch ----------------
extern "C" void kernel_launch(void* const* d_in, const int* in_sizes, int n_in,
                              void* d_out, int out_size) {
    const float* x  = (const float*)d_in[0];
    const float* w1 = (const float*)d_in[1];
    const float* b1 = (const float*)d_in[2];
    const float* w2 = (const float*)d_in[3];
    const float* b2 = (const float*)d_in[4];
    const float* wr = (const float*)d_in[5];
    const float* br = (const float*)d_in[6];
    float* out = (float*)d_out;

    setup_kernel<<<(EXPERTS*HID + 255)/256, 256>>>(b1);
    c_partial_kernel<<<dim3(DIM/256, HID/256, EXPERTS), 256>>>(w2);
    csum_kernel<<<DIM/256, 256>>>(b2);
    out_init_kernel<<<(NTOK*DIM)/256, 256>>>(out);
    routing_kernel<<<(NTOK*32)/256, 256>>>(x, wr, br);
    offsets_kernel<<<1, 1>>>();
    gemm1_kernel<<<dim3(HID/128, NTOK/128, EXPERTS), 256>>>(x, w1, b1);
    gemm2_kernel<<<dim3(DIM/128, NTOK/128, EXPERTS), 256>>>(w2, out);
}